// round 17
// baseline (speedup 1.0000x reference)
#include <cuda_runtime.h>
#include <cstdint>
#include <math.h>

#define BATCH   2
#define SEQLEN  2048
#define DMODEL  1024
#define NHEADS  16
#define DHEAD   64
#define FFDIM   4096
#define BL      (BATCH*SEQLEN)
#define NPER    (SEQLEN*DMODEL)

__device__ float g_q   [BL*DMODEL];
__device__ float g_k   [BL*DMODEL];
__device__ float g_v   [BL*DMODEL];
__device__ float g_attn[BL*DMODEL];
__device__ float g_h   [BL*DMODEL];
__device__ float g_ff1 [BL*FFDIM];
__device__ float g_ff2 [BL*DMODEL];
__device__ double g_part[BATCH*256*2];

// ----------------------------------------------------------------- helpers
__device__ __forceinline__ uint32_t f2tf32(float x) {
    uint32_t u; asm("cvt.rna.tf32.f32 %0, %1;" : "=r"(u) : "f"(x)); return u;
}
__device__ __forceinline__ void mma_tf32(float* c, const uint32_t* a, const uint32_t* b) {
    asm volatile("mma.sync.aligned.m16n8k8.row.col.f32.tf32.tf32.f32 "
        "{%0,%1,%2,%3}, {%4,%5,%6,%7}, {%8,%9}, {%0,%1,%2,%3};"
        : "+f"(c[0]), "+f"(c[1]), "+f"(c[2]), "+f"(c[3])
        : "r"(a[0]), "r"(a[1]), "r"(a[2]), "r"(a[3]), "r"(b[0]), "r"(b[1]));
}
__device__ __forceinline__ void cp_async16(uint32_t s, const void* g) {
    asm volatile("cp.async.ca.shared.global [%0], [%1], 16;" :: "r"(s), "l"(g));
}
__device__ __forceinline__ void cp_commit() { asm volatile("cp.async.commit_group;"); }
__device__ __forceinline__ void cp_wait0()  { asm volatile("cp.async.wait_group 0;"); }
__device__ __forceinline__ void cp_wait1()  { asm volatile("cp.async.wait_group 1;"); }
__device__ __forceinline__ uint32_t smem_u32(const void* p) {
    uint32_t a;
    asm("{ .reg .u64 t; cvta.to.shared.u64 t, %1; cvt.u32.u64 %0, t; }" : "=r"(a) : "l"(p));
    return a;
}

__device__ __forceinline__ float exp2s(float t) {
    t = fmaxf(t, -126.0f);
    float z = t + 12582912.0f;
    int ni = __float_as_int(z) - 0x4B400000;
    float f = t - (z - 12582912.0f);
    float p = 1.3333558e-3f;
    p = fmaf(p, f, 9.6181291e-3f); p = fmaf(p, f, 5.5504109e-2f);
    p = fmaf(p, f, 2.4022651e-1f); p = fmaf(p, f, 6.9314718e-1f);
    p = fmaf(p, f, 1.0f);
    return p * __int_as_float((ni + 127) << 23);
}

// ------------------------------------------------------------- tf32 GEMM
// Proven R8/R14 design: 128x128 tile, Kc=16, double-buffered smem, cvt on load.
#define TBM 128
#define TBN 128
#define TBK 16
#define ASTRIDE 20
#define WSTRIDE 136

__device__ __forceinline__ void gemm_body(
    const float* __restrict__ A, const float* __restrict__ W,
    const float* __restrict__ bias, float* __restrict__ C,
    int N, int K, int relu, int rnd, int bx, int by,
    uint32_t* As, uint32_t* Ws)
{
    const int tid  = threadIdx.x;
    const int lane = tid & 31;
    const int warp = tid >> 5;
    const int q = lane >> 2, r = lane & 3;
    const int wr = warp >> 2, wc = warp & 3;
    const int bm = by * TBM, bn = bx * TBN;

    const int arow = tid >> 2;
    const int akc  = (tid & 3) * 4;
    const int wrow = tid >> 5;
    const int wcol = (tid & 31) * 4;

    const float* Ag = A + (size_t)(bm + arow) * K + akc;
    const float* Wg = W + (size_t)wrow * N + bn + wcol;

    float acc[4][4][4];
    #pragma unroll
    for (int i = 0; i < 4; i++)
        #pragma unroll
        for (int j = 0; j < 4; j++)
            #pragma unroll
            for (int e = 0; e < 4; e++) acc[i][j][e] = 0.f;

    float4 ra0, ra1, rw0, rw1;
    ra0 = *(const float4*)Ag;
    ra1 = *(const float4*)(Ag + (size_t)64 * K);
    rw0 = *(const float4*)Wg;
    rw1 = *(const float4*)(Wg + (size_t)8 * N);
    Ag += TBK; Wg += (size_t)TBK * N;
    {
        uint4 pa0 = make_uint4(f2tf32(ra0.x), f2tf32(ra0.y), f2tf32(ra0.z), f2tf32(ra0.w));
        uint4 pa1 = make_uint4(f2tf32(ra1.x), f2tf32(ra1.y), f2tf32(ra1.z), f2tf32(ra1.w));
        uint4 pw0 = make_uint4(f2tf32(rw0.x), f2tf32(rw0.y), f2tf32(rw0.z), f2tf32(rw0.w));
        uint4 pw1 = make_uint4(f2tf32(rw1.x), f2tf32(rw1.y), f2tf32(rw1.z), f2tf32(rw1.w));
        *(uint4*)&As[arow*ASTRIDE + akc]        = pa0;
        *(uint4*)&As[(arow + 64)*ASTRIDE + akc] = pa1;
        *(uint4*)&Ws[wrow*WSTRIDE + wcol]       = pw0;
        *(uint4*)&Ws[(wrow + 8)*WSTRIDE + wcol] = pw1;
    }
    __syncthreads();

    const int nchunk = K / TBK;
    #pragma unroll 1
    for (int c = 0; c < nchunk; c++) {
        const int cur = c & 1;
        const bool has_next = (c + 1 < nchunk);
        const uint32_t* Ab = As + cur * (TBM*ASTRIDE);
        const uint32_t* Wb = Ws + cur * (TBK*WSTRIDE);

        if (has_next) {
            ra0 = *(const float4*)Ag;
            ra1 = *(const float4*)(Ag + (size_t)64 * K);
            rw0 = *(const float4*)Wg;
            rw1 = *(const float4*)(Wg + (size_t)8 * N);
            Ag += TBK; Wg += (size_t)TBK * N;
        }

        #pragma unroll
        for (int k8 = 0; k8 < TBK; k8 += 8) {
            uint32_t af[4][4], bf[4][2];
            #pragma unroll
            for (int tm = 0; tm < 4; tm++) {
                const int m = wr*64 + tm*16 + q;
                af[tm][0] = Ab[m*ASTRIDE + k8 + r];
                af[tm][1] = Ab[(m + 8)*ASTRIDE + k8 + r];
                af[tm][2] = Ab[m*ASTRIDE + k8 + r + 4];
                af[tm][3] = Ab[(m + 8)*ASTRIDE + k8 + r + 4];
            }
            #pragma unroll
            for (int tn = 0; tn < 4; tn++) {
                const int n = wc*32 + tn*8 + q;
                bf[tn][0] = Wb[(k8 + r)*WSTRIDE + n];
                bf[tn][1] = Wb[(k8 + r + 4)*WSTRIDE + n];
            }
            #pragma unroll
            for (int tm = 0; tm < 4; tm++)
                #pragma unroll
                for (int tn = 0; tn < 4; tn++)
                    mma_tf32(acc[tm][tn], af[tm], bf[tn]);
        }

        if (has_next) {
            uint32_t* An = As + (cur^1) * (TBM*ASTRIDE);
            uint32_t* Wn = Ws + (cur^1) * (TBK*WSTRIDE);
            uint4 pa0 = make_uint4(f2tf32(ra0.x), f2tf32(ra0.y), f2tf32(ra0.z), f2tf32(ra0.w));
            uint4 pa1 = make_uint4(f2tf32(ra1.x), f2tf32(ra1.y), f2tf32(ra1.z), f2tf32(ra1.w));
            uint4 pw0 = make_uint4(f2tf32(rw0.x), f2tf32(rw0.y), f2tf32(rw0.z), f2tf32(rw0.w));
            uint4 pw1 = make_uint4(f2tf32(rw1.x), f2tf32(rw1.y), f2tf32(rw1.z), f2tf32(rw1.w));
            *(uint4*)&An[arow*ASTRIDE + akc]        = pa0;
            *(uint4*)&An[(arow + 64)*ASTRIDE + akc] = pa1;
            *(uint4*)&Wn[wrow*WSTRIDE + wcol]       = pw0;
            *(uint4*)&Wn[(wrow + 8)*WSTRIDE + wcol] = pw1;
        }
        __syncthreads();
    }

    #pragma unroll
    for (int tm = 0; tm < 4; tm++) {
        const int row = bm + wr*64 + tm*16 + q;
        #pragma unroll
        for (int tn = 0; tn < 4; tn++) {
            const int col = bn + wc*32 + tn*8 + 2*r;
            const float2 bv = *(const float2*)(bias + col);
            float c0 = acc[tm][tn][0] + bv.x, c1 = acc[tm][tn][1] + bv.y;
            float c2 = acc[tm][tn][2] + bv.x, c3 = acc[tm][tn][3] + bv.y;
            if (relu) {
                c0 = fmaxf(c0, 0.f); c1 = fmaxf(c1, 0.f);
                c2 = fmaxf(c2, 0.f); c3 = fmaxf(c3, 0.f);
            }
            if (rnd) {
                c0 = __uint_as_float(f2tf32(c0)); c1 = __uint_as_float(f2tf32(c1));
                c2 = __uint_as_float(f2tf32(c2)); c3 = __uint_as_float(f2tf32(c3));
            }
            *(float2*)(C + (size_t)row*N + col)       = make_float2(c0, c1);
            *(float2*)(C + (size_t)(row + 8)*N + col) = make_float2(c2, c3);
        }
    }
}

__global__ __launch_bounds__(256) void tf32_gemm_bias(
    const float* __restrict__ A, const float* __restrict__ W,
    const float* __restrict__ bias, float* __restrict__ C,
    int N, int K, int relu)
{
    __shared__ uint32_t As[2*TBM*ASTRIDE];
    __shared__ uint32_t Ws[2*TBK*WSTRIDE];
    gemm_body(A, W, bias, C, N, K, relu, 0, blockIdx.x, blockIdx.y, As, Ws);
}

__global__ __launch_bounds__(256) void qkv_gemm(
    const float* __restrict__ A,
    const float* __restrict__ wq, const float* __restrict__ bq, float* __restrict__ q,
    const float* __restrict__ wk, const float* __restrict__ bk, float* __restrict__ k,
    const float* __restrict__ wv, const float* __restrict__ bv, float* __restrict__ v)
{
    __shared__ uint32_t As[2*TBM*ASTRIDE];
    __shared__ uint32_t Ws[2*TBK*WSTRIDE];
    const int z = blockIdx.z;
    const float* W    = (z == 0) ? wq : (z == 1) ? wk : wv;
    const float* bias = (z == 0) ? bq : (z == 1) ? bk : bv;
    float*       C    = (z == 0) ? q  : (z == 1) ? k  : v;
    gemm_body(A, W, bias, C, DMODEL, DMODEL, 0, 1, blockIdx.x, blockIdx.y, As, Ws);
}

// ------------------------------------------- tensor-core flash attention
// 3-stage cp.async ring for K+V (prefetch depth 2), ONE syncthreads per tile.
// K/V arrive tf32-pre-rounded from the QKV epilogue (raw-bit cp.async valid).
#define FA_BR 128
#define FA_BC 32
#define PS_STRIDE 36
#define KN_STRIDE 68
#define VS_STRIDE 72
#define KS_E (FA_BC*KN_STRIDE)          // 2176 elems / 8704 B per stage
#define VS_E (FA_BC*VS_STRIDE)          // 2304 elems / 9216 B per stage
#define PS_OFF (3*KS_E + 3*VS_E)        // 13440 elems
#define FA_SMEM ((PS_OFF + FA_BR*PS_STRIDE)*4)   // 71808 B

__global__ __launch_bounds__(256) void flash_attn_tc(
    const float* __restrict__ Q, const float* __restrict__ K,
    const float* __restrict__ V, float* __restrict__ O)
{
    extern __shared__ uint32_t dsm[];
    uint32_t* Ps = dsm + PS_OFF;

    const int tid = threadIdx.x, lane = tid & 31, warp = tid >> 5;
    const int qg = lane >> 2, r = lane & 3;
    const int b = blockIdx.z, h = blockIdx.y;
    const int q0 = blockIdx.x * FA_BR;
    const size_t base = ((size_t)b * SEQLEN) * DMODEL + h * DHEAD;
    const int mrow = warp*16 + qg;

    const int lkey = tid >> 3, lcol = (tid & 7) * 8;
    uint32_t kdst[3], vdst[3];
    #pragma unroll
    for (int s = 0; s < 3; s++) {
        kdst[s] = smem_u32(&dsm[s*KS_E + lkey*KN_STRIDE + lcol]);
        vdst[s] = smem_u32(&dsm[3*KS_E + s*VS_E + lkey*VS_STRIDE + lcol]);
    }
    const float* kg = K + base + (size_t)lkey * DMODEL + lcol;
    const float* vg = V + base + (size_t)lkey * DMODEL + lcol;

    uint32_t qf[8][4];
    {
        const float* qp  = Q + base + (size_t)(q0 + mrow) * DMODEL;
        const float* qp8 = qp + (size_t)8 * DMODEL;
        #pragma unroll
        for (int ks = 0; ks < 8; ks++) {
            qf[ks][0] = f2tf32(__ldg(qp  + ks*8 + r));
            qf[ks][1] = f2tf32(__ldg(qp8 + ks*8 + r));
            qf[ks][2] = f2tf32(__ldg(qp  + ks*8 + r + 4));
            qf[ks][3] = f2tf32(__ldg(qp8 + ks*8 + r + 4));
        }
    }

    float oc[8][4];
    #pragma unroll
    for (int nf = 0; nf < 8; nf++)
        #pragma unroll
        for (int e = 0; e < 4; e++) oc[nf][e] = 0.f;
    float m0 = -INFINITY, m1 = -INFINITY, l0 = 0.f, l1 = 0.f;
    const float SCL = 0.125f * 1.44269504f;

    // prologue: tiles 0,1 in flight (one commit group per tile)
    #pragma unroll
    for (int s = 0; s < 2; s++) {
        const float* kp = kg + (size_t)s * FA_BC * DMODEL;
        const float* vp = vg + (size_t)s * FA_BC * DMODEL;
        cp_async16(kdst[s], kp); cp_async16(kdst[s] + 16, kp + 4);
        cp_async16(vdst[s], vp); cp_async16(vdst[s] + 16, vp + 4);
        cp_commit();
    }

    const int ntiles = SEQLEN / FA_BC;
    #pragma unroll 1
    for (int kt = 0; kt < ntiles; kt++) {
        int cur = kt % 3;
        const uint32_t* Kb = dsm + cur*KS_E;
        const uint32_t* Vb = dsm + 3*KS_E + cur*VS_E;

        if (kt + 1 < ntiles) cp_wait1(); else cp_wait0();   // tile kt resident
        __syncthreads();    // visibility + buf (kt+2)%3 free (read at kt-1)

        if (kt + 2 < ntiles) {       // prefetch tile kt+2 into freed buffer
            int nxt = (kt + 2) % 3;
            const float* kp = kg + (size_t)(kt + 2) * FA_BC * DMODEL;
            const float* vp = vg + (size_t)(kt + 2) * FA_BC * DMODEL;
            cp_async16(kdst[nxt], kp); cp_async16(kdst[nxt] + 16, kp + 4);
            cp_async16(vdst[nxt], vp); cp_async16(vdst[nxt] + 16, vp + 4);
            cp_commit();
        }

        float sc[4][4];
        #pragma unroll
        for (int nf = 0; nf < 4; nf++)
            #pragma unroll
            for (int e = 0; e < 4; e++) sc[nf][e] = 0.f;

        #pragma unroll
        for (int ks = 0; ks < 8; ks++) {
            uint32_t bfr[4][2];
            #pragma unroll
            for (int nf = 0; nf < 4; nf++) {
                bfr[nf][0] = Kb[(nf*8 + qg)*KN_STRIDE + ks*8 + r];
                bfr[nf][1] = Kb[(nf*8 + qg)*KN_STRIDE + ks*8 + r + 4];
            }
            #pragma unroll
            for (int nf = 0; nf < 4; nf++)
                mma_tf32(sc[nf], qf[ks], bfr[nf]);
        }

        float rm0 = -INFINITY, rm1 = -INFINITY;
        #pragma unroll
        for (int nf = 0; nf < 4; nf++) {
            rm0 = fmaxf(rm0, fmaxf(sc[nf][0], sc[nf][1]));
            rm1 = fmaxf(rm1, fmaxf(sc[nf][2], sc[nf][3]));
        }
        rm0 = fmaxf(rm0, __shfl_xor_sync(0xffffffffu, rm0, 1));
        rm0 = fmaxf(rm0, __shfl_xor_sync(0xffffffffu, rm0, 2));
        rm1 = fmaxf(rm1, __shfl_xor_sync(0xffffffffu, rm1, 1));
        rm1 = fmaxf(rm1, __shfl_xor_sync(0xffffffffu, rm1, 2));

        const float mt0 = fmaxf(m0, rm0 * SCL);
        const float mt1 = fmaxf(m1, rm1 * SCL);
        const float c0 = exp2s(m0 - mt0);
        const float c1 = exp2s(m1 - mt1);
        m0 = mt0; m1 = mt1;

        float rs0 = 0.f, rs1 = 0.f;
        #pragma unroll
        for (int nf = 0; nf < 4; nf++) {
            const float p0 = exp2s(fmaf(sc[nf][0], SCL, -mt0));
            const float p1 = exp2s(fmaf(sc[nf][1], SCL, -mt0));
            const float p2 = exp2s(fmaf(sc[nf][2], SCL, -mt1));
            const float p3 = exp2s(fmaf(sc[nf][3], SCL, -mt1));
            rs0 += p0 + p1; rs1 += p2 + p3;
            const int colw = nf*8 + 2*r;
            *(uint2*)&Ps[(mrow)*PS_STRIDE + colw]     = make_uint2(f2tf32(p0), f2tf32(p1));
            *(uint2*)&Ps[(mrow + 8)*PS_STRIDE + colw] = make_uint2(f2tf32(p2), f2tf32(p3));
        }
        rs0 += __shfl_xor_sync(0xffffffffu, rs0, 1);
        rs0 += __shfl_xor_sync(0xffffffffu, rs0, 2);
        rs1 += __shfl_xor_sync(0xffffffffu, rs1, 1);
        rs1 += __shfl_xor_sync(0xffffffffu, rs1, 2);
        l0 = l0*c0 + rs0; l1 = l1*c1 + rs1;

        #pragma unroll
        for (int nf = 0; nf < 8; nf++) {
            oc[nf][0] *= c0; oc[nf][1] *= c0;
            oc[nf][2] *= c1; oc[nf][3] *= c1;
        }
        __syncwarp();   // Ps rows are warp-private

        #pragma unroll
        for (int ks = 0; ks < 4; ks++) {
            uint32_t af[4];
            af[0] = Ps[(mrow)*PS_STRIDE     + ks*8 + r];
            af[1] = Ps[(mrow + 8)*PS_STRIDE + ks*8 + r];
            af[2] = Ps[(mrow)*PS_STRIDE     + ks*8 + r + 4];
            af[3] = Ps[(mrow + 8)*PS_STRIDE + ks*8 + r + 4];
            #pragma unroll
            for (int nf = 0; nf < 8; nf++) {
                uint32_t bf2[2];
                bf2[0] = Vb[(ks*8 + r)*VS_STRIDE + nf*8 + qg];
                bf2[1] = Vb[(ks*8 + r + 4)*VS_STRIDE + nf*8 + qg];
                mma_tf32(oc[nf], af, bf2);
            }
        }
    }

    const float inv0 = 1.0f / l0, inv1 = 1.0f / l1;
    float* op  = O + base + (size_t)(q0 + mrow) * DMODEL;
    float* op8 = op + (size_t)8 * DMODEL;
    #pragma unroll
    for (int nf = 0; nf < 8; nf++) {
        const int col = nf*8 + 2*r;
        *(float2*)(op  + col) = make_float2(oc[nf][0]*inv0, oc[nf][1]*inv0);
        *(float2*)(op8 + col) = make_float2(oc[nf][2]*inv1, oc[nf][3]*inv1);
    }
}

// --------------------------------------------------------------- layernorm
__global__ __launch_bounds__(256) void ln_reduce(
    const float* __restrict__ a, const float* __restrict__ b, double* __restrict__ part)
{
    const int batch = blockIdx.y;
    const float* pa = a + (size_t)batch * NPER;
    const float* pb = b + (size_t)batch * NPER;
    float s = 0.f, ss = 0.f;
    const size_t stride4 = (size_t)gridDim.x * blockDim.x;
    for (size_t i = blockIdx.x*blockDim.x + threadIdx.x; i < NPER/4; i += stride4) {
        float4 va = *(const float4*)(pa + i*4);
        float4 vb = *(const float4*)(pb + i*4);
        float z0 = va.x + vb.x, z1 = va.y + vb.y;
        float z2 = va.z + vb.z, z3 = va.w + vb.w;
        s += (z0 + z1) + (z2 + z3);
        ss = fmaf(z0, z0, ss); ss = fmaf(z1, z1, ss);
        ss = fmaf(z2, z2, ss); ss = fmaf(z3, z3, ss);
    }
    __shared__ double sh[512];
    int tid = threadIdx.x;
    sh[tid] = (double)s; sh[256 + tid] = (double)ss;
    __syncthreads();
    for (int st = 128; st > 0; st >>= 1) {
        if (tid < st) { sh[tid] += sh[tid+st]; sh[256+tid] += sh[256+tid+st]; }
        __syncthreads();
    }
    if (tid == 0) {
        part[(batch*256 + blockIdx.x)*2 + 0] = sh[0];
        part[(batch*256 + blockIdx.x)*2 + 1] = sh[256];
    }
}

// fused stats+apply: each block re-reduces the 512 L2-resident partials
// (removes the separate ln_stats launch + dependency hop)
__global__ __launch_bounds__(256) void ln_apply_f(
    const float* __restrict__ a, const float* __restrict__ b,
    const double* __restrict__ part, float* __restrict__ out)
{
    const int batch = blockIdx.y;
    __shared__ double sh[512];
    int tid = threadIdx.x;
    sh[tid]       = part[(batch*256 + tid)*2 + 0];
    sh[256 + tid] = part[(batch*256 + tid)*2 + 1];
    __syncthreads();
    for (int st = 128; st > 0; st >>= 1) {
        if (tid < st) { sh[tid] += sh[tid+st]; sh[256+tid] += sh[256+tid+st]; }
        __syncthreads();
    }
    double meand = sh[0] / (double)NPER;
    double var   = sh[256] / (double)NPER - meand*meand + 1e-5;
    const float mean = (float)meand;
    const float inv  = (float)(1.0 / sqrt(var));

    size_t off = (size_t)batch * NPER + (size_t)(blockIdx.x*blockDim.x + tid)*4;
    float4 va = *(const float4*)(a + off);
    float4 vb = *(const float4*)(b + off);
    float4 o;
    o.x = (va.x + vb.x - mean) * inv;
    o.y = (va.y + vb.y - mean) * inv;
    o.z = (va.z + vb.z - mean) * inv;
    o.w = (va.w + vb.w - mean) * inv;
    *(float4*)(out + off) = o;
}

// ------------------------------------------------------------------ launch
extern "C" void kernel_launch(void* const* d_in, const int* in_sizes, int n_in,
                              void* d_out, int out_size)
{
    const float* x  = (const float*)d_in[0];
    const float* wq = (const float*)d_in[1];
    const float* bq = (const float*)d_in[2];
    const float* wk = (const float*)d_in[3];
    const float* bk = (const float*)d_in[4];
    const float* wv = (const float*)d_in[5];
    const float* bv = (const float*)d_in[6];
    const float* w1 = (const float*)d_in[7];
    const float* b1 = (const float*)d_in[8];
    const float* w2 = (const float*)d_in[9];
    const float* b2 = (const float*)d_in[10];
    float* out = (float*)d_out;

    float *q, *k, *v, *attn, *h, *ff1, *ff2;
    double* part;
    cudaGetSymbolAddress((void**)&q,    g_q);
    cudaGetSymbolAddress((void**)&k,    g_k);
    cudaGetSymbolAddress((void**)&v,    g_v);
    cudaGetSymbolAddress((void**)&attn, g_attn);
    cudaGetSymbolAddress((void**)&h,    g_h);
    cudaGetSymbolAddress((void**)&ff1,  g_ff1);
    cudaGetSymbolAddress((void**)&ff2,  g_ff2);
    cudaGetSymbolAddress((void**)&part, g_part);

    cudaFuncSetAttribute(flash_attn_tc,
        cudaFuncAttributeMaxDynamicSharedMemorySize, FA_SMEM);

    // fused QKV (tensor cores, tf32; outputs pre-rounded for cp.async)
    qkv_gemm<<<dim3(DMODEL/TBN, BL/TBM, 3), 256>>>(
        x, wq, bq, q, wk, bk, k, wv, bv, v);

    // attention (3-stage cp.async ring, software exp2)
    flash_attn_tc<<<dim3(SEQLEN/FA_BR, NHEADS, BATCH), 256, FA_SMEM>>>(q, k, v, attn);

    // residual + LN1 -> h
    ln_reduce <<<dim3(256, BATCH), 256>>>(x, attn, part);
    ln_apply_f<<<dim3(NPER/1024, BATCH), 256>>>(x, attn, part, h);

    // FFN (tensor cores, tf32)
    tf32_gemm_bias<<<dim3(FFDIM/TBN,  BL/TBM), 256>>>(h,   w1, b1, ff1, FFDIM,  DMODEL, 1);
    tf32_gemm_bias<<<dim3(DMODEL/TBN, BL/TBM), 256>>>(ff1, w2, b2, ff2, DMODEL, FFDIM,  0);

    // residual + LN2 -> out
    ln_reduce <<<dim3(256, BATCH), 256>>>(h, ff2, part);
    ln_apply_f<<<dim3(NPER/1024, BATCH), 256>>>(h, ff2, part, out);
}